// round 12
// baseline (speedup 1.0000x reference)
#include <cuda_runtime.h>
#include <cstdint>
#include <cstddef>

#define NNODES 4096
#define INDIM 256
#define HID 64
#define LOG2E 1.4426950408889634f
#define SHIFT 4.0f

// ---------------- scratch (no allocation allowed) ----------------
__device__ float g_x2[NNODES * 256];          // concat heads [N][256]
__device__ float g_srcP1[4 * NNODES];
__device__ float g_srcQ1[4 * NNODES];
__device__ float g_dstP1[4 * NNODES];
__device__ float g_dstQ1[4 * NNODES];
__device__ float g_srcP2[NNODES];
__device__ float g_srcQ2[NNODES];
__device__ float g_dstP2[NNODES];
__device__ float g_dstQ2[NNODES];
__device__ float g_pnum[2 * NNODES * 256];    // partial numerators
__device__ float g_pden[8 * NNODES];          // [z][H][N]
__device__ uint32_t g_mask[NNODES * 128];     // adjacency bitmask
__device__ uint4 g_whF1[4 * 64 * 512];        // f16 frag tensor L1: [H][c64][4ks][4ntp][32lane] uint4
__device__ uint4 g_whF2[64 * 512];            // f16 frag tensor L2

// ---------------- helpers ------------------------------------------------------
__device__ __forceinline__ uint32_t pack_f16x2(float lo, float hi) {
    uint32_t r; asm("cvt.rn.f16x2.f32 %0, %1, %2;" : "=r"(r) : "f"(hi), "f"(lo)); return r;
}
__device__ __forceinline__ uint32_t hadd2(uint32_t a, uint32_t b) {
    uint32_t r; asm("add.rn.f16x2 %0, %1, %2;" : "=r"(r) : "r"(a), "r"(b)); return r;
}
__device__ __forceinline__ uint32_t hmax2(uint32_t a, uint32_t b) {
    uint32_t r; asm("max.f16x2 %0, %1, %2;" : "=r"(r) : "r"(a), "r"(b)); return r;
}
__device__ __forceinline__ uint32_t hex2(uint32_t a) {
    uint32_t r; asm("ex2.approx.f16x2 %0, %1;" : "=r"(r) : "r"(a)); return r;
}
__device__ __forceinline__ uint32_t prmt(uint32_t a, uint32_t b, uint32_t sel) {
    uint32_t r; asm("prmt.b32 %0, %1, %2, %3;" : "=r"(r) : "r"(a), "r"(b), "r"(sel)); return r;
}
__device__ __forceinline__ void mma_f16(float* c,
                                        uint32_t a0, uint32_t a1, uint32_t a2, uint32_t a3,
                                        uint32_t b0, uint32_t b1) {
    asm volatile(
        "mma.sync.aligned.m16n8k16.row.col.f32.f16.f16.f32 "
        "{%0,%1,%2,%3}, {%4,%5,%6,%7}, {%8,%9}, {%0,%1,%2,%3};"
        : "+f"(c[0]), "+f"(c[1]), "+f"(c[2]), "+f"(c[3])
        : "r"(a0), "r"(a1), "r"(a2), "r"(a3), "r"(b0), "r"(b1));
}
__device__ __forceinline__ void cp16(void* dst, const void* src) {
    uint32_t d = (uint32_t)__cvta_generic_to_shared(dst);
    asm volatile("cp.async.cg.shared.global [%0], [%1], 16;" :: "r"(d), "l"(src));
}
#define CP_COMMIT() asm volatile("cp.async.commit_group;" ::: "memory")
#define CP_WAIT(n)  asm volatile("cp.async.wait_group %0;" :: "n"(n) : "memory")
#define ONES_F16X2  0x3C003C00u

// ---------------- fused: gemm+srcdst (blocks < ngemm) + adjacency pack --------
// gemm role: 16-row tiles. h = bx>>8, i0 = (bx&255)*16. Per thread: 1 row x 4 cols.
__global__ void __launch_bounds__(256) fused_gemm_pack_kernel(
    const float* __restrict__ X, const float* __restrict__ W,
    const float* __restrict__ B, uint4* __restrict__ YF,
    const float* __restrict__ Asrc, const float* __restrict__ Adst,
    const float* __restrict__ Ab,
    float* __restrict__ srcP, float* __restrict__ srcQ,
    float* __restrict__ dstP, float* __restrict__ dstQ,
    const int* __restrict__ adj, uint32_t* __restrict__ maskb, int ngemm)
{
    const int bx = blockIdx.x;
    const int t  = threadIdx.x;

    if (bx >= ngemm) {
        // ---- pack role ----
        const int warp = t >> 5, lane = t & 31;
        const int r = (bx - ngemm) * 8 + warp;
        const int* row = adj + (size_t)r * NNODES;
        #pragma unroll
        for (int wg = 0; wg < 4; wg++) {
            uint32_t kept = 0;
            #pragma unroll
            for (int ww = 0; ww < 32; ww++) {
                int v = row[(wg * 32 + ww) * 32 + lane];
                uint32_t b = __ballot_sync(0xffffffffu, v > 0);
                if (lane == ww) kept = b;
            }
            maskb[(size_t)r * 128 + wg * 32 + lane] = kept;
        }
        return;
    }

    // ---- gemm role: 16 rows x 64 cols, 3-deep cp.async pipeline ----
    const int h   = bx >> 8;
    const int i0  = (bx & 255) * 16;
    const int dg  = t & 15;        // d-group of 4 cols
    const int row = t >> 4;        // local row 0..15

    __shared__ float Xs[4][16][16];
    __shared__ float Ws[4][16][64];

    const float* Wh = W + (size_t)h * INDIM * HID;
    const int xrow = t >> 2, xseg = t & 3;     // t < 64 stages X
    const int wrow = t >> 4, wseg = t & 15;    // all stage W

    auto stage = [&](int buf, int kc) {
        if (t < 64)
            cp16(&Xs[buf][xrow][xseg * 4], X + (size_t)(i0 + xrow) * INDIM + kc + xseg * 4);
        cp16(&Ws[buf][wrow][wseg * 4], Wh + (size_t)(kc + wrow) * HID + wseg * 4);
    };

    stage(0, 0);  CP_COMMIT();
    stage(1, 16); CP_COMMIT();
    stage(2, 32); CP_COMMIT();

    float acc[4] = {};
    #pragma unroll
    for (int kk = 0; kk < 16; kk++) {
        CP_WAIT(2);
        __syncthreads();
        if (kk + 3 < 16) stage((kk + 3) & 3, (kk + 3) * 16);
        CP_COMMIT();

        const int buf = kk & 3;
        #pragma unroll
        for (int k4 = 0; k4 < 4; k4++) {
            float4 xv = *(const float4*)(&Xs[buf][row][k4 * 4]);
            float4 w0 = *(const float4*)(&Ws[buf][k4 * 4 + 0][dg * 4]);
            float4 w1 = *(const float4*)(&Ws[buf][k4 * 4 + 1][dg * 4]);
            float4 w2 = *(const float4*)(&Ws[buf][k4 * 4 + 2][dg * 4]);
            float4 w3 = *(const float4*)(&Ws[buf][k4 * 4 + 3][dg * 4]);
            acc[0] += xv.x * w0.x; acc[1] += xv.x * w0.y; acc[2] += xv.x * w0.z; acc[3] += xv.x * w0.w;
            acc[0] += xv.y * w1.x; acc[1] += xv.y * w1.y; acc[2] += xv.y * w1.z; acc[3] += xv.y * w1.w;
            acc[0] += xv.z * w2.x; acc[1] += xv.z * w2.y; acc[2] += xv.z * w2.z; acc[3] += xv.z * w2.w;
            acc[0] += xv.w * w3.x; acc[1] += xv.w * w3.y; acc[2] += xv.w * w3.z; acc[3] += xv.w * w3.w;
        }
    }

    // fold bias
    float4 bv = *(const float4*)(B + h * HID + dg * 4);
    acc[0] += bv.x; acc[1] += bv.y; acc[2] += bv.z; acc[3] += bv.w;

    // src/dst projection: partial dot + 16-lane butterfly over dg
    {
        float4 asv = *(const float4*)(Asrc + h * HID + dg * 4);
        float4 adv = *(const float4*)(Adst + h * HID + dg * 4);
        float sv  = acc[0] * asv.x + acc[1] * asv.y + acc[2] * asv.z + acc[3] * asv.w;
        float dvv = acc[0] * adv.x + acc[1] * adv.y + acc[2] * adv.z + acc[3] * adv.w;
        #pragma unroll
        for (int o = 1; o < 16; o <<= 1) {
            sv  += __shfl_xor_sync(0xffffffffu, sv, o);
            dvv += __shfl_xor_sync(0xffffffffu, dvv, o);
        }
        if (dg == 0) {
            const int gi = h * NNODES + i0 + row;
            float u = (sv + Ab[h]) * LOG2E;
            float v = dvv * LOG2E;
            srcP[gi] = u - SHIFT;
            srcQ[gi] = 0.2f * u - SHIFT;
            dstP[gi] = v;
            dstQ[gi] = 0.2f * v;
        }
    }

    // fragment tensor: pair rows (2w, 2w+1) via shfl_xor 16 (t and t^16 = row pair)
    float accO[4];
    #pragma unroll
    for (int c = 0; c < 4; c++) accO[c] = __shfl_xor_sync(0xffffffffu, acc[c], 16);

    if ((t & 16) == 0) {   // even-row threads store the pair
        uint32_t* fb = (uint32_t*)(YF + (size_t)h * 64 * 512);
        const int jp = i0 + row;           // even global row
        const int c64 = jp >> 6;
        const int ks = (jp >> 4) & 3;
        const int rr = jp & 15;
        #pragma unroll
        for (int c = 0; c < 4; c++) {
            const int d = dg * 4 + c;
            const int ntp = d >> 4;
            const int sub = (d >> 3) & 1;
            const int lanei = (d & 7) * 4 + ((rr & 7) >> 1);
            const int word = sub * 2 + (rr >> 3);
            uint32_t val = pack_f16x2(acc[c], accO[c]);
            size_t idx = (((size_t)c64 * 4 + ks) * 4 + ntp) * 32 + lanei;
            fb[idx * 4 + word] = val;
        }
    }
}

// ---------------- fused attention: 64-j chunks, 4-stage pipe, unroll x4 -------
__global__ void __launch_bounds__(256, 2) attn_mma_kernel(
    const uint4* __restrict__ whF,      // [H][64][4][4][32] uint4
    const float* __restrict__ srcP, const float* __restrict__ srcQ,  // [H][N]
    const float* __restrict__ dstP, const float* __restrict__ dstQ,  // [H][N]
    const uint32_t* __restrict__ maskb, // [N][128]
    float* __restrict__ pnum,           // [z][N][pcols]
    float* __restrict__ pden,           // [z][H][N]
    int pcols, int nheads)
{
    __shared__ alignas(16) uint4 bfragq[4][4][4][32];  // 4-stage, 8KB each
    __shared__ alignas(16) uint2 dsts2[1024];          // permuted (P2,Q2) j-pairs

    const int h    = blockIdx.y;
    const int t    = threadIdx.x;
    const int lane = t & 31;
    const int warp = t >> 5;
    const int gid  = lane >> 2;
    const int tig  = lane & 3;
    const int i0   = blockIdx.x * 128;
    const int z       = blockIdx.z;
    const int jsplit  = gridDim.z;
    const int nchunks = (NNODES / 64) / jsplit;
    const int jc0     = z * nchunks * 64;

    const int hN = h * NNODES;
    // stage dst pairs once, PERMUTED: within each 8-group, old m -> 2*(m&3)+(m>>2)
    for (int q = t; q < nchunks * 32; q += 256) {
        int j = jc0 + 2 * q;
        uint2 v;
        v.x = pack_f16x2(dstP[hN + j], dstP[hN + j + 1]);
        v.y = pack_f16x2(dstQ[hN + j], dstQ[hN + j + 1]);
        int m = q & 7;
        int pos = (q & ~7) | ((m & 3) << 1) | (m >> 2);
        dsts2[pos] = v;
    }

    const int iA = i0 + warp * 16 + gid;
    const int iB = iA + 8;
    const uint32_t srcP2A = pack_f16x2(srcP[hN + iA], srcP[hN + iA]);
    const uint32_t srcQ2A = pack_f16x2(srcQ[hN + iA], srcQ[hN + iA]);
    const uint32_t srcP2B = pack_f16x2(srcP[hN + iB], srcP[hN + iB]);
    const uint32_t srcQ2B = pack_f16x2(srcQ[hN + iB], srcQ[hN + iB]);
    const uint2* mA2 = (const uint2*)(maskb + (size_t)iA * 128 + (jc0 >> 5));
    const uint2* mB2 = (const uint2*)(maskb + (size_t)iB * 128 + (jc0 >> 5));

    const uint4* gsrc = whF + ((size_t)h * 64 + (jc0 >> 6)) * 512;

    float acc[9][4];
    #pragma unroll
    for (int n = 0; n < 9; n++)
        #pragma unroll
        for (int r = 0; r < 4; r++) acc[n][r] = 0.f;

    // prologue: stage chunks 0,1,2
    #pragma unroll
    for (int s = 0; s < 3; s++) {
        uint4* d0 = &bfragq[s][0][0][0];
        cp16(d0 + t, gsrc + (size_t)s * 512 + t);
        cp16(d0 + t + 256, gsrc + (size_t)s * 512 + t + 256);
        CP_COMMIT();
    }

    const int tshift = 2 * tig;
    for (int cg = 0; cg < nchunks; cg += 4) {
        uint4 mAa = *(const uint4*)(mA2 + cg);
        uint4 mAb = *(const uint4*)(mA2 + cg + 2);
        uint4 mBa = *(const uint4*)(mB2 + cg);
        uint4 mBb = *(const uint4*)(mB2 + cg + 2);
        uint32_t wAx[4] = {mAa.x, mAa.z, mAb.x, mAb.z};
        uint32_t wAy[4] = {mAa.y, mAa.w, mAb.y, mAb.w};
        uint32_t wBx[4] = {mBa.x, mBa.z, mBb.x, mBb.z};
        uint32_t wBy[4] = {mBa.y, mBa.w, mBb.y, mBb.w};

        #pragma unroll
        for (int cc = 0; cc < 4; cc++) {
            const int chunk = cg + cc;
            CP_WAIT(2);
            __syncthreads();
            if (chunk + 3 < nchunks) {
                uint4* dn = &bfragq[(cc + 3) & 3][0][0][0];
                const uint4* sn = gsrc + (size_t)(chunk + 3) * 512;
                cp16(dn + t, sn + t);
                cp16(dn + t + 256, sn + t + 256);
            }
            CP_COMMIT();

            #pragma unroll
            for (int ks = 0; ks < 4; ks++) {
                uint32_t pAm = ((ks < 2) ? wAx[cc] : wAy[cc]) >> ((ks & 1) * 16 + tshift);
                uint32_t pBm = ((ks < 2) ? wBx[cc] : wBy[cc]) >> ((ks & 1) * 16 + tshift);
                uint32_t sA1 = pAm << 7,  sA2 = pAm << 14;
                uint32_t sB1 = pBm << 7,  sB2 = pBm << 14;
                uint32_t mskA0 = prmt(sA1, sA2, 0xDD88u);
                uint32_t mskA1 = prmt(sA1, sA2, 0xEE99u);
                uint32_t mskB0 = prmt(sB1, sB2, 0xDD88u);
                uint32_t mskB1 = prmt(sB1, sB2, 0xEE99u);

                uint4 dd = *(const uint4*)(dsts2 + chunk * 32 + ks * 8 + tshift);

                uint32_t eA0 = hex2(hmax2(hadd2(srcP2A, dd.x), hadd2(srcQ2A, dd.y))) & mskA0;
                uint32_t eA1 = hex2(hmax2(hadd2(srcP2A, dd.z), hadd2(srcQ2A, dd.w))) & mskA1;
                uint32_t eB0 = hex2(hmax2(hadd2(srcP2B, dd.x), hadd2(srcQ2B, dd.y))) & mskB0;
                uint32_t eB1 = hex2(hmax2(hadd2(srcP2B, dd.z), hadd2(srcQ2B, dd.w))) & mskB1;

                const uint4* bk = &bfragq[cc][ks][0][lane];
                #pragma unroll
                for (int ntp = 0; ntp < 4; ntp++) {
                    uint4 b = bk[ntp * 32];
                    mma_f16(acc[2 * ntp],     eA0, eB0, eA1, eB1, b.x, b.y);
                    mma_f16(acc[2 * ntp + 1], eA0, eB0, eA1, eB1, b.z, b.w);
                }
                mma_f16(acc[8], eA0, eB0, eA1, eB1, ONES_F16X2, ONES_F16X2);
            }
        }
    }

    const float denA = acc[8][0];
    const float denB = acc[8][2];

    float* pA = pnum + ((size_t)z * NNODES + iA) * pcols + h * 64 + 2 * tig;
    float* pB = pnum + ((size_t)z * NNODES + iB) * pcols + h * 64 + 2 * tig;
    #pragma unroll
    for (int nt = 0; nt < 8; nt++) {
        float2 va, vb;
        va.x = acc[nt][0]; va.y = acc[nt][1];
        vb.x = acc[nt][2]; vb.y = acc[nt][3];
        *(float2*)(pA + nt * 8) = va;
        *(float2*)(pB + nt * 8) = vb;
    }
    if (tig == 0) {
        pden[((size_t)z * nheads + h) * NNODES + iA] = denA;
        pden[((size_t)z * nheads + h) * NNODES + iB] = denB;
    }
}

// ---------------- partial reduce + softmax divide + elu (templated ILP) -------
template<int ZN, int COLS, int CSHIFT, int H>
__global__ void reduce_kernel(const float* __restrict__ pnum,
                              const float* __restrict__ pden,
                              float* __restrict__ out)
{
    int idx = blockIdx.x * blockDim.x + threadIdx.x;
    int i = idx >> CSHIFT;
    int c = (idx & ((1 << CSHIFT) - 1)) << 3;
    int h = c >> 6;

    float den = 0.f;
    #pragma unroll
    for (int zz = 0; zz < ZN; zz++)
        den += pden[((size_t)zz * H + h) * NNODES + i];

    float4 a0, a1;
    {
        const float* p = pnum + (size_t)i * COLS + c;
        a0 = *(const float4*)p;
        a1 = *(const float4*)(p + 4);
    }
    #pragma unroll
    for (int zz = 1; zz < ZN; zz++) {
        const float* p = pnum + ((size_t)zz * NNODES + i) * COLS + c;
        float4 b0 = *(const float4*)p;
        float4 b1 = *(const float4*)(p + 4);
        a0.x += b0.x; a0.y += b0.y; a0.z += b0.z; a0.w += b0.w;
        a1.x += b1.x; a1.y += b1.y; a1.z += b1.z; a1.w += b1.w;
    }
    float inv = 1.f / den;
    float v[8] = {a0.x * inv, a0.y * inv, a0.z * inv, a0.w * inv,
                  a1.x * inv, a1.y * inv, a1.z * inv, a1.w * inv};
    #pragma unroll
    for (int r = 0; r < 8; r++) v[r] = (v[r] > 0.f) ? v[r] : expm1f(v[r]);
    float4 o0 = {v[0], v[1], v[2], v[3]};
    float4 o1 = {v[4], v[5], v[6], v[7]};
    float* op = out + (size_t)i * COLS + c;
    *(float4*)op = o0;
    *(float4*)(op + 4) = o1;
}

// ---------------- launch ------------------------------------------------------
extern "C" void kernel_launch(void* const* d_in, const int* in_sizes, int n_in,
                              void* d_out, int out_size)
{
    const float* h      = (const float*)d_in[0];
    const int*   adj    = (const int*)  d_in[1];
    const float* Wh     = (const float*)d_in[2];
    const float* bWh    = (const float*)d_in[3];
    const float* a_src  = (const float*)d_in[4];
    const float* a_dst  = (const float*)d_in[5];
    const float* a_b    = (const float*)d_in[6];
    const float* Wo     = (const float*)d_in[7];
    const float* bWo    = (const float*)d_in[8];
    const float* ao_src = (const float*)d_in[9];
    const float* ao_dst = (const float*)d_in[10];
    const float* ao_b   = (const float*)d_in[11];
    float* out = (float*)d_out;

    float *x2, *pnum, *pden;
    float *sP1, *sQ1, *dP1, *dQ1, *sP2, *sQ2, *dP2, *dQ2;
    uint32_t* maskb;
    uint4 *whF1, *whF2;
    cudaGetSymbolAddress((void**)&x2,   g_x2);
    cudaGetSymbolAddress((void**)&sP1, g_srcP1);
    cudaGetSymbolAddress((void**)&sQ1, g_srcQ1);
    cudaGetSymbolAddress((void**)&dP1, g_dstP1);
    cudaGetSymbolAddress((void**)&dQ1, g_dstQ1);
    cudaGetSymbolAddress((void**)&sP2, g_srcP2);
    cudaGetSymbolAddress((void**)&sQ2, g_srcQ2);
    cudaGetSymbolAddress((void**)&dP2, g_dstP2);
    cudaGetSymbolAddress((void**)&dQ2, g_dstQ2);
    cudaGetSymbolAddress((void**)&pnum, g_pnum);
    cudaGetSymbolAddress((void**)&pden, g_pden);
    cudaGetSymbolAddress((void**)&maskb, g_mask);
    cudaGetSymbolAddress((void**)&whF1, g_whF1);
    cudaGetSymbolAddress((void**)&whF2, g_whF2);

    // Layer 1: gemm 16-row tiles (1024 blocks) + pack (512 blocks) fused
    fused_gemm_pack_kernel<<<1024 + 512, 256>>>(h, Wh, bWh, whF1,
                                                a_src, a_dst, a_b,
                                                sP1, sQ1, dP1, dQ1,
                                                adj, maskb, 1024);
    attn_mma_kernel<<<dim3(NNODES / 128, 4, 2), 256>>>(whF1, sP1, sQ1, dP1, dQ1, maskb, pnum, pden, 256, 4);
    reduce_kernel<2, 256, 5, 4><<<(NNODES * 32) / 256, 256>>>(pnum, pden, x2);

    // Layer 2 (jsplit=8): gemm 256 blocks
    fused_gemm_pack_kernel<<<256, 256>>>(x2, Wo, bWo, whF2,
                                         ao_src, ao_dst, ao_b,
                                         sP2, sQ2, dP2, dQ2,
                                         adj, maskb, 256);
    attn_mma_kernel<<<dim3(NNODES / 128, 1, 8), 256>>>(whF2, sP2, sQ2, dP2, dQ2, maskb, pnum, pden, 64, 1);
    reduce_kernel<8, 64, 3, 1><<<(NNODES * 8) / 256, 256>>>(pnum, pden, out);
}

// round 13
// speedup vs baseline: 1.1972x; 1.1972x over previous
#include <cuda_runtime.h>
#include <cstdint>
#include <cstddef>

#define NNODES 4096
#define INDIM 256
#define HID 64
#define LOG2E 1.4426950408889634f
#define SHIFT 4.0f

// ---------------- scratch (no allocation allowed) ----------------
__device__ float g_x2[NNODES * 256];          // concat heads [N][256]
__device__ float g_srcP1[4 * NNODES];
__device__ float g_srcQ1[4 * NNODES];
__device__ float g_dstP1[4 * NNODES];
__device__ float g_dstQ1[4 * NNODES];
__device__ float g_srcP2[NNODES];
__device__ float g_srcQ2[NNODES];
__device__ float g_dstP2[NNODES];
__device__ float g_dstQ2[NNODES];
__device__ float g_pnum[2 * NNODES * 256];    // partial numerators
__device__ float g_pden[8 * NNODES];          // [z][H][N]
__device__ uint32_t g_mask[NNODES * 128];     // adjacency bitmask
__device__ uint4 g_whF1[4 * 64 * 512];        // f16 frag tensor L1: [H][c64][4ks][4ntp][32lane] uint4
__device__ uint4 g_whF2[64 * 512];            // f16 frag tensor L2

// ---------------- helpers ------------------------------------------------------
__device__ __forceinline__ uint32_t pack_f16x2(float lo, float hi) {
    uint32_t r; asm("cvt.rn.f16x2.f32 %0, %1, %2;" : "=r"(r) : "f"(hi), "f"(lo)); return r;
}
__device__ __forceinline__ uint32_t hadd2(uint32_t a, uint32_t b) {
    uint32_t r; asm("add.rn.f16x2 %0, %1, %2;" : "=r"(r) : "r"(a), "r"(b)); return r;
}
__device__ __forceinline__ uint32_t hmax2(uint32_t a, uint32_t b) {
    uint32_t r; asm("max.f16x2 %0, %1, %2;" : "=r"(r) : "r"(a), "r"(b)); return r;
}
__device__ __forceinline__ uint32_t hex2(uint32_t a) {
    uint32_t r; asm("ex2.approx.f16x2 %0, %1;" : "=r"(r) : "r"(a)); return r;
}
__device__ __forceinline__ uint32_t prmt(uint32_t a, uint32_t b, uint32_t sel) {
    uint32_t r; asm("prmt.b32 %0, %1, %2, %3;" : "=r"(r) : "r"(a), "r"(b), "r"(sel)); return r;
}
__device__ __forceinline__ void mma_f16(float* c,
                                        uint32_t a0, uint32_t a1, uint32_t a2, uint32_t a3,
                                        uint32_t b0, uint32_t b1) {
    asm volatile(
        "mma.sync.aligned.m16n8k16.row.col.f32.f16.f16.f32 "
        "{%0,%1,%2,%3}, {%4,%5,%6,%7}, {%8,%9}, {%0,%1,%2,%3};"
        : "+f"(c[0]), "+f"(c[1]), "+f"(c[2]), "+f"(c[3])
        : "r"(a0), "r"(a1), "r"(a2), "r"(a3), "r"(b0), "r"(b1));
}
__device__ __forceinline__ void cp16(void* dst, const void* src) {
    uint32_t d = (uint32_t)__cvta_generic_to_shared(dst);
    asm volatile("cp.async.cg.shared.global [%0], [%1], 16;" :: "r"(d), "l"(src));
}
#define CP_COMMIT() asm volatile("cp.async.commit_group;" ::: "memory")
#define CP_WAIT(n)  asm volatile("cp.async.wait_group %0;" :: "n"(n) : "memory")
#define ONES_F16X2  0x3C003C00u

// ---------------- fused: gemm+srcdst (blocks < ngemm) + adjacency pack --------
// gemm role: 64-row tiles, 2-stage cp.async (round-10 proven-fastest variant).
__global__ void __launch_bounds__(256) fused_gemm_pack_kernel(
    const float* __restrict__ X, const float* __restrict__ W,
    const float* __restrict__ B, uint4* __restrict__ YF,
    const float* __restrict__ Asrc, const float* __restrict__ Adst,
    const float* __restrict__ Ab,
    float* __restrict__ srcP, float* __restrict__ srcQ,
    float* __restrict__ dstP, float* __restrict__ dstQ,
    const int* __restrict__ adj, uint32_t* __restrict__ maskb, int ngemm)
{
    const int bx = blockIdx.x;
    const int t  = threadIdx.x;

    if (bx >= ngemm) {
        // ---- pack role ----
        const int warp = t >> 5, lane = t & 31;
        const int r = (bx - ngemm) * 8 + warp;
        const int* row = adj + (size_t)r * NNODES;
        #pragma unroll
        for (int wg = 0; wg < 4; wg++) {
            uint32_t kept = 0;
            #pragma unroll
            for (int ww = 0; ww < 32; ww++) {
                int v = row[(wg * 32 + ww) * 32 + lane];
                uint32_t b = __ballot_sync(0xffffffffu, v > 0);
                if (lane == ww) kept = b;
            }
            maskb[(size_t)r * 128 + wg * 32 + lane] = kept;
        }
        return;
    }

    // ---- gemm role (2-stage cp.async, 64-row tiles) ----
    const int h  = bx >> 6;
    const int i0 = (bx & 63) * 64;
    const int dg = t & 15;
    const int ig = t >> 4;

    __shared__ float Xs[2][64][16];
    __shared__ float Ws[2][16][64];

    const float* Wh = W + (size_t)h * INDIM * HID;
    const int xrow = t >> 2, xseg = t & 3;
    const int wrow = t >> 4, wseg = t & 15;

    auto stage = [&](int buf, int kc) {
        cp16(&Xs[buf][xrow][xseg * 4], X + (size_t)(i0 + xrow) * INDIM + kc + xseg * 4);
        cp16(&Ws[buf][wrow][wseg * 4], Wh + (size_t)(kc + wrow) * HID + wseg * 4);
    };

    stage(0, 0);
    CP_COMMIT();

    float acc[4][4] = {};
    for (int kk = 0; kk < INDIM / 16; kk++) {
        if (kk + 1 < INDIM / 16) {
            stage((kk + 1) & 1, (kk + 1) * 16);
            CP_COMMIT();
            CP_WAIT(1);
        } else {
            CP_WAIT(0);
        }
        __syncthreads();
        const int buf = kk & 1;
        #pragma unroll
        for (int k = 0; k < 16; k++) {
            float4 wv = *(const float4*)(&Ws[buf][k][dg * 4]);
            float x0 = Xs[buf][ig * 4 + 0][k];
            float x1 = Xs[buf][ig * 4 + 1][k];
            float x2 = Xs[buf][ig * 4 + 2][k];
            float x3 = Xs[buf][ig * 4 + 3][k];
            acc[0][0] += x0 * wv.x; acc[0][1] += x0 * wv.y; acc[0][2] += x0 * wv.z; acc[0][3] += x0 * wv.w;
            acc[1][0] += x1 * wv.x; acc[1][1] += x1 * wv.y; acc[1][2] += x1 * wv.z; acc[1][3] += x1 * wv.w;
            acc[2][0] += x2 * wv.x; acc[2][1] += x2 * wv.y; acc[2][2] += x2 * wv.z; acc[2][3] += x2 * wv.w;
            acc[3][0] += x3 * wv.x; acc[3][1] += x3 * wv.y; acc[3][2] += x3 * wv.z; acc[3][3] += x3 * wv.w;
        }
        __syncthreads();
    }

    // fold bias into acc
    float4 bv = *(const float4*)(B + h * HID + dg * 4);
    #pragma unroll
    for (int ii = 0; ii < 4; ii++) {
        acc[ii][0] += bv.x; acc[ii][1] += bv.y;
        acc[ii][2] += bv.z; acc[ii][3] += bv.w;
    }

    // src/dst projections: per-thread partial dot + 16-lane butterfly
    {
        float4 asv = *(const float4*)(Asrc + h * HID + dg * 4);
        float4 adv = *(const float4*)(Adst + h * HID + dg * 4);
        float sv[4], dvv[4];
        #pragma unroll
        for (int ii = 0; ii < 4; ii++) {
            sv[ii]  = acc[ii][0] * asv.x + acc[ii][1] * asv.y + acc[ii][2] * asv.z + acc[ii][3] * asv.w;
            dvv[ii] = acc[ii][0] * adv.x + acc[ii][1] * adv.y + acc[ii][2] * adv.z + acc[ii][3] * adv.w;
        }
        #pragma unroll
        for (int o = 1; o < 16; o <<= 1) {
            #pragma unroll
            for (int ii = 0; ii < 4; ii++) {
                sv[ii]  += __shfl_xor_sync(0xffffffffu, sv[ii], o);
                dvv[ii] += __shfl_xor_sync(0xffffffffu, dvv[ii], o);
            }
        }
        if (dg == 0) {
            const float abh = Ab[h];
            #pragma unroll
            for (int ii = 0; ii < 4; ii++) {
                const int gi = h * NNODES + i0 + ig * 4 + ii;
                float u = (sv[ii] + abh) * LOG2E;
                float v = dvv[ii] * LOG2E;
                srcP[gi] = u - SHIFT;
                srcQ[gi] = 0.2f * u - SHIFT;
                dstP[gi] = v;
                dstQ[gi] = 0.2f * v;
            }
        }
    }

    // paired f16 fragment tensor: [h][c64][ks][ntp][lane] uint4 (bias already in acc)
    uint32_t* fb = (uint32_t*)(YF + (size_t)h * 64 * 512);
    #pragma unroll
    for (int c = 0; c < 4; c++) {
        const int d = dg * 4 + c;
        const int ntp = d >> 4;
        const int sub = (d >> 3) & 1;
        const int lnb = (d & 7) * 4;
        #pragma unroll
        for (int p = 0; p < 2; p++) {
            const int jp = i0 + ig * 4 + 2 * p;
            const int c64 = jp >> 6;
            const int ks = (jp >> 4) & 3;
            const int rr = jp & 15;
            const int lanei = lnb + ((rr & 7) >> 1);
            const int word = sub * 2 + (rr >> 3);
            uint32_t val = pack_f16x2(acc[2 * p][c], acc[2 * p + 1][c]);
            size_t idx = (((size_t)c64 * 4 + ks) * 4 + ntp) * 32 + lanei;
            fb[idx * 4 + word] = val;
        }
    }
}

// ---------------- fused attention: 64-j chunks, 4-stage pipe, unroll x4 -------
__global__ void __launch_bounds__(256, 2) attn_mma_kernel(
    const uint4* __restrict__ whF,      // [H][64][4][4][32] uint4
    const float* __restrict__ srcP, const float* __restrict__ srcQ,  // [H][N]
    const float* __restrict__ dstP, const float* __restrict__ dstQ,  // [H][N]
    const uint32_t* __restrict__ maskb, // [N][128]
    float* __restrict__ pnum,           // [z][N][pcols]
    float* __restrict__ pden,           // [z][H][N]
    int pcols, int nheads)
{
    __shared__ alignas(16) uint4 bfragq[4][4][4][32];  // 4-stage, 8KB each
    __shared__ alignas(16) uint2 dsts2[1024];          // permuted (P2,Q2) j-pairs

    const int h    = blockIdx.y;
    const int t    = threadIdx.x;
    const int lane = t & 31;
    const int warp = t >> 5;
    const int gid  = lane >> 2;
    const int tig  = lane & 3;
    const int i0   = blockIdx.x * 128;
    const int z       = blockIdx.z;
    const int jsplit  = gridDim.z;
    const int nchunks = (NNODES / 64) / jsplit;
    const int jc0     = z * nchunks * 64;

    const int hN = h * NNODES;
    // stage dst pairs once, PERMUTED: within each 8-group, old m -> 2*(m&3)+(m>>2)
    for (int q = t; q < nchunks * 32; q += 256) {
        int j = jc0 + 2 * q;
        uint2 v;
        v.x = pack_f16x2(dstP[hN + j], dstP[hN + j + 1]);
        v.y = pack_f16x2(dstQ[hN + j], dstQ[hN + j + 1]);
        int m = q & 7;
        int pos = (q & ~7) | ((m & 3) << 1) | (m >> 2);
        dsts2[pos] = v;
    }

    const int iA = i0 + warp * 16 + gid;
    const int iB = iA + 8;
    const uint32_t srcP2A = pack_f16x2(srcP[hN + iA], srcP[hN + iA]);
    const uint32_t srcQ2A = pack_f16x2(srcQ[hN + iA], srcQ[hN + iA]);
    const uint32_t srcP2B = pack_f16x2(srcP[hN + iB], srcP[hN + iB]);
    const uint32_t srcQ2B = pack_f16x2(srcQ[hN + iB], srcQ[hN + iB]);
    const uint2* mA2 = (const uint2*)(maskb + (size_t)iA * 128 + (jc0 >> 5));
    const uint2* mB2 = (const uint2*)(maskb + (size_t)iB * 128 + (jc0 >> 5));

    const uint4* gsrc = whF + ((size_t)h * 64 + (jc0 >> 6)) * 512;

    float acc[9][4];
    #pragma unroll
    for (int n = 0; n < 9; n++)
        #pragma unroll
        for (int r = 0; r < 4; r++) acc[n][r] = 0.f;

    // prologue: stage chunks 0,1,2
    #pragma unroll
    for (int s = 0; s < 3; s++) {
        uint4* d0 = &bfragq[s][0][0][0];
        cp16(d0 + t, gsrc + (size_t)s * 512 + t);
        cp16(d0 + t + 256, gsrc + (size_t)s * 512 + t + 256);
        CP_COMMIT();
    }

    const int tshift = 2 * tig;
    for (int cg = 0; cg < nchunks; cg += 4) {
        uint4 mAa = *(const uint4*)(mA2 + cg);
        uint4 mAb = *(const uint4*)(mA2 + cg + 2);
        uint4 mBa = *(const uint4*)(mB2 + cg);
        uint4 mBb = *(const uint4*)(mB2 + cg + 2);
        uint32_t wAx[4] = {mAa.x, mAa.z, mAb.x, mAb.z};
        uint32_t wAy[4] = {mAa.y, mAa.w, mAb.y, mAb.w};
        uint32_t wBx[4] = {mBa.x, mBa.z, mBb.x, mBb.z};
        uint32_t wBy[4] = {mBa.y, mBa.w, mBb.y, mBb.w};

        #pragma unroll
        for (int cc = 0; cc < 4; cc++) {
            const int chunk = cg + cc;
            CP_WAIT(2);
            __syncthreads();
            if (chunk + 3 < nchunks) {
                uint4* dn = &bfragq[(cc + 3) & 3][0][0][0];
                const uint4* sn = gsrc + (size_t)(chunk + 3) * 512;
                cp16(dn + t, sn + t);
                cp16(dn + t + 256, sn + t + 256);
            }
            CP_COMMIT();

            #pragma unroll
            for (int ks = 0; ks < 4; ks++) {
                uint32_t pAm = ((ks < 2) ? wAx[cc] : wAy[cc]) >> ((ks & 1) * 16 + tshift);
                uint32_t pBm = ((ks < 2) ? wBx[cc] : wBy[cc]) >> ((ks & 1) * 16 + tshift);
                uint32_t sA1 = pAm << 7,  sA2 = pAm << 14;
                uint32_t sB1 = pBm << 7,  sB2 = pBm << 14;
                uint32_t mskA0 = prmt(sA1, sA2, 0xDD88u);
                uint32_t mskA1 = prmt(sA1, sA2, 0xEE99u);
                uint32_t mskB0 = prmt(sB1, sB2, 0xDD88u);
                uint32_t mskB1 = prmt(sB1, sB2, 0xEE99u);

                uint4 dd = *(const uint4*)(dsts2 + chunk * 32 + ks * 8 + tshift);

                uint32_t eA0 = hex2(hmax2(hadd2(srcP2A, dd.x), hadd2(srcQ2A, dd.y))) & mskA0;
                uint32_t eA1 = hex2(hmax2(hadd2(srcP2A, dd.z), hadd2(srcQ2A, dd.w))) & mskA1;
                uint32_t eB0 = hex2(hmax2(hadd2(srcP2B, dd.x), hadd2(srcQ2B, dd.y))) & mskB0;
                uint32_t eB1 = hex2(hmax2(hadd2(srcP2B, dd.z), hadd2(srcQ2B, dd.w))) & mskB1;

                const uint4* bk = &bfragq[cc][ks][0][lane];
                #pragma unroll
                for (int ntp = 0; ntp < 4; ntp++) {
                    uint4 b = bk[ntp * 32];
                    mma_f16(acc[2 * ntp],     eA0, eB0, eA1, eB1, b.x, b.y);
                    mma_f16(acc[2 * ntp + 1], eA0, eB0, eA1, eB1, b.z, b.w);
                }
                mma_f16(acc[8], eA0, eB0, eA1, eB1, ONES_F16X2, ONES_F16X2);
            }
        }
    }

    const float denA = acc[8][0];
    const float denB = acc[8][2];

    float* pA = pnum + ((size_t)z * NNODES + iA) * pcols + h * 64 + 2 * tig;
    float* pB = pnum + ((size_t)z * NNODES + iB) * pcols + h * 64 + 2 * tig;
    #pragma unroll
    for (int nt = 0; nt < 8; nt++) {
        float2 va, vb;
        va.x = acc[nt][0]; va.y = acc[nt][1];
        vb.x = acc[nt][2]; vb.y = acc[nt][3];
        *(float2*)(pA + nt * 8) = va;
        *(float2*)(pB + nt * 8) = vb;
    }
    if (tig == 0) {
        pden[((size_t)z * nheads + h) * NNODES + iA] = denA;
        pden[((size_t)z * nheads + h) * NNODES + iB] = denB;
    }
}

// ---------------- partial reduce + softmax divide + elu (templated ILP) -------
template<int ZN, int COLS, int CSHIFT, int H>
__global__ void reduce_kernel(const float* __restrict__ pnum,
                              const float* __restrict__ pden,
                              float* __restrict__ out)
{
    int idx = blockIdx.x * blockDim.x + threadIdx.x;
    int i = idx >> CSHIFT;
    int c = (idx & ((1 << CSHIFT) - 1)) << 3;
    int h = c >> 6;

    float den = 0.f;
    #pragma unroll
    for (int zz = 0; zz < ZN; zz++)
        den += pden[((size_t)zz * H + h) * NNODES + i];

    float4 a0, a1;
    {
        const float* p = pnum + (size_t)i * COLS + c;
        a0 = *(const float4*)p;
        a1 = *(const float4*)(p + 4);
    }
    #pragma unroll
    for (int zz = 1; zz < ZN; zz++) {
        const float* p = pnum + ((size_t)zz * NNODES + i) * COLS + c;
        float4 b0 = *(const float4*)p;
        float4 b1 = *(const float4*)(p + 4);
        a0.x += b0.x; a0.y += b0.y; a0.z += b0.z; a0.w += b0.w;
        a1.x += b1.x; a1.y += b1.y; a1.z += b1.z; a1.w += b1.w;
    }
    float inv = 1.f / den;
    float v[8] = {a0.x * inv, a0.y * inv, a0.z * inv, a0.w * inv,
                  a1.x * inv, a1.y * inv, a1.z * inv, a1.w * inv};
    #pragma unroll
    for (int r = 0; r < 8; r++) v[r] = (v[r] > 0.f) ? v[r] : expm1f(v[r]);
    float4 o0 = {v[0], v[1], v[2], v[3]};
    float4 o1 = {v[4], v[5], v[6], v[7]};
    float* op = out + (size_t)i * COLS + c;
    *(float4*)op = o0;
    *(float4*)(op + 4) = o1;
}

// ---------------- launch ------------------------------------------------------
extern "C" void kernel_launch(void* const* d_in, const int* in_sizes, int n_in,
                              void* d_out, int out_size)
{
    const float* h      = (const float*)d_in[0];
    const int*   adj    = (const int*)  d_in[1];
    const float* Wh     = (const float*)d_in[2];
    const float* bWh    = (const float*)d_in[3];
    const float* a_src  = (const float*)d_in[4];
    const float* a_dst  = (const float*)d_in[5];
    const float* a_b    = (const float*)d_in[6];
    const float* Wo     = (const float*)d_in[7];
    const float* bWo    = (const float*)d_in[8];
    const float* ao_src = (const float*)d_in[9];
    const float* ao_dst = (const float*)d_in[10];
    const float* ao_b   = (const float*)d_in[11];
    float* out = (float*)d_out;

    float *x2, *pnum, *pden;
    float *sP1, *sQ1, *dP1, *dQ1, *sP2, *sQ2, *dP2, *dQ2;
    uint32_t* maskb;
    uint4 *whF1, *whF2;
    cudaGetSymbolAddress((void**)&x2,   g_x2);
    cudaGetSymbolAddress((void**)&sP1, g_srcP1);
    cudaGetSymbolAddress((void**)&sQ1, g_srcQ1);
    cudaGetSymbolAddress((void**)&dP1, g_dstP1);
    cudaGetSymbolAddress((void**)&dQ1, g_dstQ1);
    cudaGetSymbolAddress((void**)&sP2, g_srcP2);
    cudaGetSymbolAddress((void**)&sQ2, g_srcQ2);
    cudaGetSymbolAddress((void**)&dP2, g_dstP2);
    cudaGetSymbolAddress((void**)&dQ2, g_dstQ2);
    cudaGetSymbolAddress((void**)&pnum, g_pnum);
    cudaGetSymbolAddress((void**)&pden, g_pden);
    cudaGetSymbolAddress((void**)&maskb, g_mask);
    cudaGetSymbolAddress((void**)&whF1, g_whF1);
    cudaGetSymbolAddress((void**)&whF2, g_whF2);

    // Layer 1: gemm 64-row tiles (256 blocks) + pack (512 blocks) fused
    fused_gemm_pack_kernel<<<256 + 512, 256>>>(h, Wh, bWh, whF1,
                                               a_src, a_dst, a_b,
                                               sP1, sQ1, dP1, dQ1,
                                               adj, maskb, 256);
    attn_mma_kernel<<<dim3(NNODES / 128, 4, 2), 256>>>(whF1, sP1, sQ1, dP1, dQ1, maskb, pnum, pden, 256, 4);
    reduce_kernel<2, 256, 5, 4><<<(NNODES * 32) / 256, 256>>>(pnum, pden, x2);

    // Layer 2 (jsplit=8): gemm 64 blocks
    fused_gemm_pack_kernel<<<64, 256>>>(x2, Wo, bWo, whF2,
                                        ao_src, ao_dst, ao_b,
                                        sP2, sQ2, dP2, dQ2,
                                        adj, maskb, 64);
    attn_mma_kernel<<<dim3(NNODES / 128, 1, 8), 256>>>(whF2, sP2, sQ2, dP2, dQ2, maskb, pnum, pden, 64, 1);
    reduce_kernel<8, 64, 3, 1><<<(NNODES * 8) / 256, 256>>>(pnum, pden, out);
}